// round 9
// baseline (speedup 1.0000x reference)
#include <cuda_runtime.h>
#include <cuda_fp16.h>
#include <cstdint>

// BinaryConv2d via Winograd F(2x2,3x3) + mma.sync HMMA, fp16 data, fp32 accum.
// R9: warp tile 32x16, CTA 64 tiles x 64 oc, <=128 regs -> 2 CTAs/SM.

#define NB 32
#define CI 128
#define CO 256
#define HH 56
#define HP 58
#define PIXN (HH*HH)
#define TPI  784              // 28*28 tiles per image
#define NTILE (NB*TPI)        // 25088
#define NITER 32              // 16 xi-nu * 2 chunks of k=64
#define STAGES 4

// padded NHWC fp16
__device__ __half g_xp[(size_t)NB*HP*HP*128];
// Winograd-transformed input U[xi*4+nu][tile][c]
__device__ __half g_u[(size_t)16*NTILE*128];
// Winograd-transformed binarized weights V[xi*4+nu][oc][c]
__device__ __half g_v[(size_t)16*CO*128];

// ---------------- stage 1: pad + fp16 ----------------
__global__ __launch_bounds__(256)
void transform_x_kernel(const float* __restrict__ x) {
    __shared__ float s[128][57];
    const int hp = blockIdx.x % HP;
    const int n  = blockIdx.x / HP;
    const int tid = threadIdx.x;
    const bool interior_h = (hp >= 1 && hp <= HH);

    if (interior_h) {
        const int h = hp - 1;
        const float* src = x + ((size_t)n * CI * HH + h) * HH;
        for (int idx = tid; idx < CI * HH; idx += 256) {
            int c = idx / HH, w = idx - (idx / HH) * HH;
            s[c][w] = src[(size_t)c * PIXN + w];
        }
    }
    __syncthreads();

    const int c  = tid & 127;
    const int wh = tid >> 7;
    __half* ob = g_xp + ((size_t)(n * HP + hp) * HP) * 128 + c;
#pragma unroll 4
    for (int wp = wh * 29; wp < wh * 29 + 29; wp++) {
        float v = 0.0f;
        if (interior_h && wp >= 1 && wp <= HH) v = s[c][wp - 1];
        ob[(size_t)wp * 128] = __float2half_rn(v);
    }
}

// ---------------- stage 2: input Winograd transform ----------------
__global__ __launch_bounds__(256)
void winograd_x_kernel() {
    int idx = blockIdx.x * 256 + threadIdx.x;    // over NTILE*128
    int c = idx & 127;
    int t = idx >> 7;
    int n  = t / TPI;
    int r  = t - n * TPI;
    int ti = r / 28, tj = r - (r / 28) * 28;

    const __half* base = g_xp + ((size_t)(n * HP + 2 * ti) * HP + 2 * tj) * 128 + c;
    float d[4][4];
#pragma unroll
    for (int i = 0; i < 4; i++)
#pragma unroll
        for (int s = 0; s < 4; s++)
            d[i][s] = __half2float(base[(size_t)(i * HP + s) * 128]);

    float tr[4][4];
#pragma unroll
    for (int s = 0; s < 4; s++) {
        tr[0][s] = d[0][s] - d[2][s];
        tr[1][s] = d[1][s] + d[2][s];
        tr[2][s] = d[2][s] - d[1][s];
        tr[3][s] = d[1][s] - d[3][s];
    }
    float u[4][4];
#pragma unroll
    for (int i = 0; i < 4; i++) {
        u[i][0] = tr[i][0] - tr[i][2];
        u[i][1] = tr[i][1] + tr[i][2];
        u[i][2] = tr[i][2] - tr[i][1];
        u[i][3] = tr[i][1] - tr[i][3];
    }
#pragma unroll
    for (int xi = 0; xi < 4; xi++)
#pragma unroll
        for (int nu = 0; nu < 4; nu++)
            g_u[((size_t)(xi * 4 + nu) * NTILE + t) * 128 + c] = __float2half_rn(u[xi][nu]);
}

// ---------------- stage 3: weight Winograd transform ----------------
__global__ __launch_bounds__(256)
void winograd_w_kernel(const float* __restrict__ w) {
    int idx = blockIdx.x * 256 + threadIdx.x;    // over CO*CI
    if (idx >= CO * CI) return;
    int oc = idx >> 7;
    int c  = idx & 127;
    float g[3][3];
#pragma unroll
    for (int r = 0; r < 3; r++)
#pragma unroll
        for (int s = 0; s < 3; s++)
            g[r][s] = (w[((size_t)(oc * CI + c)) * 9 + r * 3 + s] >= 0.0f) ? 1.0f : -1.0f;
    float gg[4][3];
#pragma unroll
    for (int s = 0; s < 3; s++) {
        gg[0][s] = g[0][s];
        gg[1][s] = 0.5f * (g[0][s] + g[1][s] + g[2][s]);
        gg[2][s] = 0.5f * (g[0][s] - g[1][s] + g[2][s]);
        gg[3][s] = g[2][s];
    }
#pragma unroll
    for (int i = 0; i < 4; i++) {
        float v0 = gg[i][0];
        float v1 = 0.5f * (gg[i][0] + gg[i][1] + gg[i][2]);
        float v2 = 0.5f * (gg[i][0] - gg[i][1] + gg[i][2]);
        float v3 = gg[i][2];
        g_v[((size_t)(i * 4 + 0) * CO + oc) * 128 + c] = __float2half_rn(v0);
        g_v[((size_t)(i * 4 + 1) * CO + oc) * 128 + c] = __float2half_rn(v1);
        g_v[((size_t)(i * 4 + 2) * CO + oc) * 128 + c] = __float2half_rn(v2);
        g_v[((size_t)(i * 4 + 3) * CO + oc) * 128 + c] = __float2half_rn(v3);
    }
}

// ---------------- main kernel ----------------
__device__ __forceinline__ uint32_t smem_u32(const void* p) {
    uint32_t a;
    asm("{ .reg .u64 t; cvta.to.shared.u64 t, %1; cvt.u32.u64 %0, t; }" : "=r"(a) : "l"(p));
    return a;
}
__device__ __forceinline__ void cp16(uint32_t dst, const void* src) {
    asm volatile("cp.async.cg.shared.global [%0], [%1], 16;" :: "r"(dst), "l"(src));
}
#define CP_COMMIT() asm volatile("cp.async.commit_group;" ::: "memory")
#define CP_WAIT2()  asm volatile("cp.async.wait_group 2;" ::: "memory")

__device__ __forceinline__ void ldsm4(uint32_t* r, uint32_t addr) {
    asm volatile("ldmatrix.sync.aligned.m8n8.x4.shared.b16 {%0,%1,%2,%3}, [%4];"
        : "=r"(r[0]), "=r"(r[1]), "=r"(r[2]), "=r"(r[3]) : "r"(addr));
}
__device__ __forceinline__ void mma16816(float* c, const uint32_t* a, uint32_t b0, uint32_t b1) {
    asm volatile("mma.sync.aligned.m16n8k16.row.col.f32.f16.f16.f32 "
        "{%0,%1,%2,%3}, {%4,%5,%6,%7}, {%8,%9}, {%0,%1,%2,%3};"
        : "+f"(c[0]), "+f"(c[1]), "+f"(c[2]), "+f"(c[3])
        : "r"(a[0]), "r"(a[1]), "r"(a[2]), "r"(a[3]), "r"(b0), "r"(b1));
}

#define A_ST  8192                   // 64 tiles x 64 k x fp16
#define B_ST  8192                   // 64 oc   x 64 k x fp16
#define ST_BYTES (A_ST + B_ST)       // 16 KB / stage
#define SMEM_SZ (STAGES * ST_BYTES)  // 64 KB -> 2 CTAs/SM

// inverse-transform row coefficients: A^T rows
__device__ const float c_AT[2][4] = {{1.f, 1.f, 1.f, 0.f}, {0.f, 1.f, -1.f, -1.f}};

__global__ __launch_bounds__(256, 2)
void binconv_wino_kernel(const float* __restrict__ bias, float* __restrict__ out) {
    extern __shared__ char smem[];
    const uint32_t sb = smem_u32(smem);

    const int tid  = threadIdx.x;
    const int wid  = tid >> 5;
    const int lane = tid & 31;
    const int t0   = blockIdx.x * 64;      // tile block
    const int ocb  = blockIdx.y * 64;      // oc block

    // ---- producer addressing ----
    const int arow = tid >> 3;             // 0..31; second unit via +32
    const int seg  = tid & 7;
    const uint32_t adst0 = sb + (uint32_t)(seg * 64 + arow) * 16;           // + 512 for +32
    const uint32_t bdst0 = sb + A_ST + (uint32_t)(seg * 64 + arow) * 16;

    // warp tiling: 2 (tiles) x 4 (oc); warp tile 32 tiles x 16 oc
    const int wm = (wid & 1) * 32;
    const int wn = (wid >> 1) * 16;

    float Y[4][2][2][4];                   // [ij][mi][nb][e]
#pragma unroll
    for (int ij = 0; ij < 4; ij++)
#pragma unroll
        for (int mi = 0; mi < 2; mi++)
#pragma unroll
            for (int nb = 0; nb < 2; nb++)
#pragma unroll
                for (int e = 0; e < 4; e++) Y[ij][mi][nb][e] = 0.0f;

    float macc[2][2][4];
#pragma unroll
    for (int mi = 0; mi < 2; mi++)
#pragma unroll
        for (int nb = 0; nb < 2; nb++)
#pragma unroll
            for (int e = 0; e < 4; e++) macc[mi][nb][e] = 0.0f;

    auto issue = [&](int kk) {
        if (kk < NITER) {
            const uint32_t soff = (uint32_t)(kk % STAGES) * ST_BYTES;
            const int xn  = kk >> 1;       // xi*4+nu
            const int sub = kk & 1;
            const __half* ua = g_u + ((size_t)xn * NTILE + t0 + arow) * 128 + sub * 64 + seg * 8;
            cp16(adst0 + soff, ua);
            cp16(adst0 + 512 + soff, ua + (size_t)32 * 128);
            const __half* vb = g_v + ((size_t)xn * CO + ocb + arow) * 128 + sub * 64 + seg * 8;
            cp16(bdst0 + soff, vb);
            cp16(bdst0 + 512 + soff, vb + (size_t)32 * 128);
        }
        CP_COMMIT();
    };

    issue(0); issue(1); issue(2);

    const uint32_t a_lrow = (uint32_t)((lane >> 4) * 64 + (lane & 15)) * 16;
    const uint32_t b_lrow = (uint32_t)(((lane >> 3) & 1) * 64 + (lane & 7) + ((lane >> 4) << 3)) * 16;

    for (int kk = 0; kk < NITER; kk++) {
        const uint32_t soff = (uint32_t)(kk % STAGES) * ST_BYTES;
        CP_WAIT2();
        __syncthreads();
        issue(kk + 3);

#pragma unroll
        for (int kb = 0; kb < 4; kb++) {
            uint32_t af[2][4], bf[4];
#pragma unroll
            for (int mi = 0; mi < 2; mi++)
                ldsm4(af[mi], sb + soff + kb * 2048 + a_lrow + (uint32_t)(wm + mi * 16) * 16);
            ldsm4(bf, sb + A_ST + soff + kb * 2048 + b_lrow + (uint32_t)wn * 16);
#pragma unroll
            for (int mi = 0; mi < 2; mi++) {
                mma16816(macc[mi][0], af[mi], bf[0], bf[1]);
                mma16816(macc[mi][1], af[mi], bf[2], bf[3]);
            }
        }

        if (kk & 1) {
            // fold M[xi][nu] into Y with A^T coefficients, then clear macc
            const int xn = kk >> 1;
            const int xi = xn >> 2, nu = xn & 3;
#pragma unroll
            for (int i = 0; i < 2; i++) {
                const float fi = c_AT[i][xi];
                if (fi != 0.0f) {
#pragma unroll
                    for (int j = 0; j < 2; j++) {
                        const float f = fi * c_AT[j][nu];
                        if (f != 0.0f) {
#pragma unroll
                            for (int mi = 0; mi < 2; mi++)
#pragma unroll
                                for (int nb = 0; nb < 2; nb++)
#pragma unroll
                                    for (int e = 0; e < 4; e++)
                                        Y[i * 2 + j][mi][nb][e] = fmaf(f, macc[mi][nb][e], Y[i * 2 + j][mi][nb][e]);
                        }
                    }
                }
            }
#pragma unroll
            for (int mi = 0; mi < 2; mi++)
#pragma unroll
                for (int nb = 0; nb < 2; nb++)
#pragma unroll
                    for (int e = 0; e < 4; e++) macc[mi][nb][e] = 0.0f;
        }
    }

    // ---------------- epilogue: inverse-transformed outputs -> NCHW + bias ----------------
    const int qr  = lane >> 2;             // 0..7
    const int oc2 = (lane & 3) * 2;

    float2 bv[2];
#pragma unroll
    for (int nb = 0; nb < 2; nb++)
        bv[nb] = *(const float2*)(bias + ocb + wn + nb * 8 + oc2);

#pragma unroll
    for (int mi = 0; mi < 2; mi++) {
#pragma unroll
        for (int rh = 0; rh < 2; rh++) {
            const int t  = t0 + wm + mi * 16 + rh * 8 + qr;
            const int n2 = t / TPI;
            const int rr = t - n2 * TPI;
            const int ti = rr / 28;
            const int tj = rr - ti * 28;
            float* ob0 = out + ((size_t)n2 * CO) * PIXN + (size_t)(2 * ti) * HH + 2 * tj;
#pragma unroll
            for (int i = 0; i < 2; i++) {
#pragma unroll
                for (int j = 0; j < 2; j++) {
                    float* ob = ob0 + i * HH + j;
#pragma unroll
                    for (int nb = 0; nb < 2; nb++) {
                        const int oc = wn + nb * 8 + oc2;
                        ob[(size_t)(ocb + oc) * PIXN]     = Y[i * 2 + j][mi][nb][rh * 2 + 0] + bv[nb].x;
                        ob[(size_t)(ocb + oc + 1) * PIXN] = Y[i * 2 + j][mi][nb][rh * 2 + 1] + bv[nb].y;
                    }
                }
            }
        }
    }
}

// ---------------- launch ----------------
extern "C" void kernel_launch(void* const* d_in, const int* in_sizes, int n_in,
                              void* d_out, int out_size) {
    const float* x      = (const float*)d_in[0];
    const float* weight = (const float*)d_in[1];
    const float* bias   = (const float*)d_in[2];
    float* out          = (float*)d_out;

    cudaFuncSetAttribute(binconv_wino_kernel,
                         cudaFuncAttributeMaxDynamicSharedMemorySize, SMEM_SZ);

    transform_x_kernel<<<NB * HP, 256>>>(x);
    winograd_x_kernel<<<NTILE * 128 / 256, 256>>>();
    winograd_w_kernel<<<(CO * CI + 255) / 256, 256>>>(weight);

    dim3 grid(NTILE / 64, CO / 64);
    binconv_wino_kernel<<<grid, 256, SMEM_SZ>>>(bias, out);
}

// round 10
// speedup vs baseline: 1.1111x; 1.1111x over previous
#include <cuda_runtime.h>
#include <cuda_fp16.h>
#include <cstdint>

// BinaryConv2d via Winograd F(2x2,3x3) + mma.sync HMMA.
// R10: pure per-xn GEMM (no in-register fold) -> M buffer -> separate inverse kernel.

#define NB 32
#define CI 128
#define CO 256
#define HH 56
#define HP 58
#define PIXN (HH*HH)
#define TPI  784              // 28*28 tiles per image
#define NTILE (NB*TPI)        // 25088

// padded NHWC fp16
__device__ __half g_xp[(size_t)NB*HP*HP*128];
// Winograd input U[xn][tile][c]
__device__ __align__(16) __half g_u[(size_t)16*NTILE*128];
// Winograd binarized weights V[xn][oc][c]
__device__ __align__(16) __half g_v[(size_t)16*CO*128];
// GEMM result M[xn][tile][oc]
__device__ __align__(16) __half g_m[(size_t)16*NTILE*CO];

// ---------------- stage 1: pad + fp16 ----------------
__global__ __launch_bounds__(256)
void transform_x_kernel(const float* __restrict__ x) {
    __shared__ float s[128][57];
    const int hp = blockIdx.x % HP;
    const int n  = blockIdx.x / HP;
    const int tid = threadIdx.x;
    const bool interior_h = (hp >= 1 && hp <= HH);

    if (interior_h) {
        const int h = hp - 1;
        const float* src = x + ((size_t)n * CI * HH + h) * HH;
        for (int idx = tid; idx < CI * HH; idx += 256) {
            int c = idx / HH, w = idx - (idx / HH) * HH;
            s[c][w] = src[(size_t)c * PIXN + w];
        }
    }
    __syncthreads();

    const int c  = tid & 127;
    const int wh = tid >> 7;
    __half* ob = g_xp + ((size_t)(n * HP + hp) * HP) * 128 + c;
#pragma unroll 4
    for (int wp = wh * 29; wp < wh * 29 + 29; wp++) {
        float v = 0.0f;
        if (interior_h && wp >= 1 && wp <= HH) v = s[c][wp - 1];
        ob[(size_t)wp * 128] = __float2half_rn(v);
    }
}

// ---------------- stage 2: input Winograd transform ----------------
__global__ __launch_bounds__(256)
void winograd_x_kernel() {
    int idx = blockIdx.x * 256 + threadIdx.x;    // over NTILE*128
    int c = idx & 127;
    int t = idx >> 7;
    int n  = t / TPI;
    int r  = t - n * TPI;
    int ti = r / 28, tj = r - (r / 28) * 28;

    const __half* base = g_xp + ((size_t)(n * HP + 2 * ti) * HP + 2 * tj) * 128 + c;
    float d[4][4];
#pragma unroll
    for (int i = 0; i < 4; i++)
#pragma unroll
        for (int s = 0; s < 4; s++)
            d[i][s] = __half2float(base[(size_t)(i * HP + s) * 128]);

    float tr[4][4];
#pragma unroll
    for (int s = 0; s < 4; s++) {
        tr[0][s] = d[0][s] - d[2][s];
        tr[1][s] = d[1][s] + d[2][s];
        tr[2][s] = d[2][s] - d[1][s];
        tr[3][s] = d[1][s] - d[3][s];
    }
    float u[4][4];
#pragma unroll
    for (int i = 0; i < 4; i++) {
        u[i][0] = tr[i][0] - tr[i][2];
        u[i][1] = tr[i][1] + tr[i][2];
        u[i][2] = tr[i][2] - tr[i][1];
        u[i][3] = tr[i][1] - tr[i][3];
    }
#pragma unroll
    for (int xi = 0; xi < 4; xi++)
#pragma unroll
        for (int nu = 0; nu < 4; nu++)
            g_u[((size_t)(xi * 4 + nu) * NTILE + t) * 128 + c] = __float2half_rn(u[xi][nu]);
}

// ---------------- stage 3: weight Winograd transform ----------------
__global__ __launch_bounds__(256)
void winograd_w_kernel(const float* __restrict__ w) {
    int idx = blockIdx.x * 256 + threadIdx.x;    // over CO*CI
    if (idx >= CO * CI) return;
    int oc = idx >> 7;
    int c  = idx & 127;
    float g[3][3];
#pragma unroll
    for (int r = 0; r < 3; r++)
#pragma unroll
        for (int s = 0; s < 3; s++)
            g[r][s] = (w[((size_t)(oc * CI + c)) * 9 + r * 3 + s] >= 0.0f) ? 1.0f : -1.0f;
    float gg[4][3];
#pragma unroll
    for (int s = 0; s < 3; s++) {
        gg[0][s] = g[0][s];
        gg[1][s] = 0.5f * (g[0][s] + g[1][s] + g[2][s]);
        gg[2][s] = 0.5f * (g[0][s] - g[1][s] + g[2][s]);
        gg[3][s] = g[2][s];
    }
#pragma unroll
    for (int i = 0; i < 4; i++) {
        float v0 = gg[i][0];
        float v1 = 0.5f * (gg[i][0] + gg[i][1] + gg[i][2]);
        float v2 = 0.5f * (gg[i][0] - gg[i][1] + gg[i][2]);
        float v3 = gg[i][2];
        g_v[((size_t)(i * 4 + 0) * CO + oc) * 128 + c] = __float2half_rn(v0);
        g_v[((size_t)(i * 4 + 1) * CO + oc) * 128 + c] = __float2half_rn(v1);
        g_v[((size_t)(i * 4 + 2) * CO + oc) * 128 + c] = __float2half_rn(v2);
        g_v[((size_t)(i * 4 + 3) * CO + oc) * 128 + c] = __float2half_rn(v3);
    }
}

// ---------------- GEMM kernel ----------------
__device__ __forceinline__ uint32_t smem_u32(const void* p) {
    uint32_t a;
    asm("{ .reg .u64 t; cvta.to.shared.u64 t, %1; cvt.u32.u64 %0, t; }" : "=r"(a) : "l"(p));
    return a;
}
__device__ __forceinline__ void cp16(uint32_t dst, const void* src) {
    asm volatile("cp.async.cg.shared.global [%0], [%1], 16;" :: "r"(dst), "l"(src));
}
#define CP_COMMIT() asm volatile("cp.async.commit_group;" ::: "memory")
#define CP_WAIT(n)  asm volatile("cp.async.wait_group %0;" :: "n"(n) : "memory")

__device__ __forceinline__ void ldsm4(uint32_t* r, uint32_t addr) {
    asm volatile("ldmatrix.sync.aligned.m8n8.x4.shared.b16 {%0,%1,%2,%3}, [%4];"
        : "=r"(r[0]), "=r"(r[1]), "=r"(r[2]), "=r"(r[3]) : "r"(addr));
}
__device__ __forceinline__ void mma16816(float* c, const uint32_t* a, uint32_t b0, uint32_t b1) {
    asm volatile("mma.sync.aligned.m16n8k16.row.col.f32.f16.f16.f32 "
        "{%0,%1,%2,%3}, {%4,%5,%6,%7}, {%8,%9}, {%0,%1,%2,%3};"
        : "+f"(c[0]), "+f"(c[1]), "+f"(c[2]), "+f"(c[3])
        : "r"(a[0]), "r"(a[1]), "r"(a[2]), "r"(a[3]), "r"(b0), "r"(b1));
}

#define A_ST  16384                  // 128 tiles x 64 k x fp16
#define B_ST  32768                  // 256 oc   x 64 k x fp16
#define ST_BYTES (A_ST + B_ST)       // 48 KB / stage
#define SMEM_SZ (2 * ST_BYTES)       // 96 KB, 2 stages

__global__ __launch_bounds__(512, 1)
void binconv_wino_gemm(void) {
    extern __shared__ char smem[];
    const uint32_t sb = smem_u32(smem);

    const int tid  = threadIdx.x;
    const int wid  = tid >> 5;
    const int lane = tid & 31;
    const int t0   = blockIdx.x * 128;
    const int xn   = blockIdx.y;

    // ---- producers ----
    // A: 1024 16B-units/stage: u = tid + j*512 -> pix = u>>3, seg = u&7
    const __half* ua0 = g_u + ((size_t)xn * NTILE + t0) * 128;
    const __half* a_src[2];
    uint32_t adst[2];
#pragma unroll
    for (int j = 0; j < 2; j++) {
        int u = tid + j * 512;
        int pix = u >> 3, seg = u & 7;
        a_src[j] = ua0 + (size_t)pix * 128 + seg * 8;
        adst[j]  = sb + (uint32_t)(seg * 128 + pix) * 16;
    }
    // B: 2048 units/stage: u = tid + j*512 -> oc = u>>3, seg = u&7
    const __half* vb0 = g_v + (size_t)xn * CO * 128;
    const __half* b_src[4];
    uint32_t bdst[4];
#pragma unroll
    for (int j = 0; j < 4; j++) {
        int u = tid + j * 512;
        int oc = u >> 3, seg = u & 7;
        b_src[j] = vb0 + (size_t)oc * 128 + seg * 8;
        bdst[j]  = sb + A_ST + (uint32_t)(seg * 256 + oc) * 16;
    }

    // issue both K-chunks immediately
#pragma unroll
    for (int sub = 0; sub < 2; sub++) {
        const uint32_t soff = sub * ST_BYTES;
#pragma unroll
        for (int j = 0; j < 2; j++) cp16(adst[j] + soff, a_src[j] + sub * 64);
#pragma unroll
        for (int j = 0; j < 4; j++) cp16(bdst[j] + soff, b_src[j] + sub * 64);
        CP_COMMIT();
    }

    // warp tiling: 4 (M) x 4 (N); warp tile 32 x 64
    const int wm = (wid & 3) * 32;
    const int wn = (wid >> 2) * 64;

    float acc[2][8][4];
#pragma unroll
    for (int mi = 0; mi < 2; mi++)
#pragma unroll
        for (int nb = 0; nb < 8; nb++)
#pragma unroll
            for (int j = 0; j < 4; j++) acc[mi][nb][j] = 0.0f;

    const uint32_t a_lrow = (uint32_t)((lane >> 4) * 128 + (lane & 15)) * 16;
    const uint32_t b_lrow = (uint32_t)(((lane >> 3) & 1) * 256 + (lane & 7) + ((lane >> 4) << 3)) * 16;

#pragma unroll
    for (int sub = 0; sub < 2; sub++) {
        if (sub == 0) { CP_WAIT(1); } else { CP_WAIT(0); }
        __syncthreads();
        const uint32_t soff = sub * ST_BYTES;
#pragma unroll
        for (int kb = 0; kb < 4; kb++) {
            uint32_t af[2][4], bf[4][4];
#pragma unroll
            for (int mi = 0; mi < 2; mi++)
                ldsm4(af[mi], sb + soff + kb * 4096 + a_lrow + (uint32_t)(wm + mi * 16) * 16);
#pragma unroll
            for (int nj = 0; nj < 4; nj++)
                ldsm4(bf[nj], sb + A_ST + soff + kb * 8192 + b_lrow + (uint32_t)(wn + nj * 16) * 16);
#pragma unroll
            for (int mi = 0; mi < 2; mi++)
#pragma unroll
                for (int nb = 0; nb < 8; nb++) {
                    const uint32_t* bp = bf[nb >> 1];
                    if (nb & 1) mma16816(acc[mi][nb], af[mi], bp[2], bp[3]);
                    else        mma16816(acc[mi][nb], af[mi], bp[0], bp[1]);
                }
        }
    }

    // ---- epilogue: store M to g_m (fp16, coalesced half2) ----
    const int qr  = lane >> 2;
    const int oc2 = (lane & 3) * 2;
#pragma unroll
    for (int mi = 0; mi < 2; mi++) {
#pragma unroll
        for (int half = 0; half < 2; half++) {
            const int row = wm + mi * 16 + half * 8 + qr;
            __half2* mp = (__half2*)(g_m + ((size_t)xn * NTILE + t0 + row) * 256);
#pragma unroll
            for (int nb = 0; nb < 8; nb++) {
                const int oc = wn + nb * 8 + oc2;
                mp[oc >> 1] = __floats2half2_rn(acc[mi][nb][half * 2 + 0],
                                                acc[mi][nb][half * 2 + 1]);
            }
        }
    }
}

// ---------------- inverse transform kernel ----------------
// block = (n, ti, ocg); smem transpose of M, coalesced NCHW output + bias.
#define SMB 140                       // bytes per (xn,tj) smem row (70 halfs, odd stride)
#define INV_SMEM (16*28*SMB)          // 62720 B

__global__ __launch_bounds__(256)
void binconv_wino_inverse(const float* __restrict__ bias, float* __restrict__ out) {
    extern __shared__ char sm[];
    const int tid = threadIdx.x;
    const int bi  = blockIdx.x;           // n*28 + ti
    const int n   = bi / 28;
    const int ti  = bi - n * 28;
    const int ocb = blockIdx.y * 64;
    const int tbase = n * TPI + ti * 28;

    // ---- load M[16][28 tj][64 oc] into smem (16B gmem loads, 4B smem stores) ----
    for (int u = tid; u < 16 * 28 * 8; u += 256) {
        int xn = u / 224;
        int r  = u - xn * 224;
        int tj = r >> 3;
        int sg = r & 7;
        const uint4 v = *(const uint4*)(g_m + ((size_t)xn * NTILE + tbase + tj) * 256 + ocb + sg * 8);
        char* d = sm + (xn * 28 + tj) * SMB + sg * 16;
        ((uint32_t*)d)[0] = v.x;
        ((uint32_t*)d)[1] = v.y;
        ((uint32_t*)d)[2] = v.z;
        ((uint32_t*)d)[3] = v.w;
    }
    __syncthreads();

    // ---- compute A^T M A per (tj, oc-pair), write coalesced float2 ----
    for (int p = tid; p < 28 * 32; p += 256) {
        const int tj  = p % 28;
        const int o2  = p / 28;          // oc pair index
        float m[16][2];
#pragma unroll
        for (int xn = 0; xn < 16; xn++) {
            __half2 hv = *(__half2*)(sm + (xn * 28 + tj) * SMB + o2 * 4);
            m[xn][0] = __low2float(hv);
            m[xn][1] = __high2float(hv);
        }
#pragma unroll
        for (int l = 0; l < 2; l++) {
            float r0[4], r1[4];
#pragma unroll
            for (int nu = 0; nu < 4; nu++) {
                r0[nu] = m[0 * 4 + nu][l] + m[1 * 4 + nu][l] + m[2 * 4 + nu][l];
                r1[nu] = m[1 * 4 + nu][l] - m[2 * 4 + nu][l] - m[3 * 4 + nu][l];
            }
            const int oc = ocb + o2 * 2 + l;
            const float b = __ldg(&bias[oc]);
            float* ob = out + ((size_t)n * CO + oc) * PIXN + (size_t)(2 * ti) * HH + 2 * tj;
            float2 y0 = {r0[0] + r0[1] + r0[2] + b, r0[1] - r0[2] - r0[3] + b};
            float2 y1 = {r1[0] + r1[1] + r1[2] + b, r1[1] - r1[2] - r1[3] + b};
            *(float2*)ob        = y0;
            *(float2*)(ob + HH) = y1;
        }
    }
}

// ---------------- launch ----------------
extern "C" void kernel_launch(void* const* d_in, const int* in_sizes, int n_in,
                              void* d_out, int out_size) {
    const float* x      = (const float*)d_in[0];
    const float* weight = (const float*)d_in[1];
    const float* bias   = (const float*)d_in[2];
    float* out          = (float*)d_out;

    cudaFuncSetAttribute(binconv_wino_gemm,
                         cudaFuncAttributeMaxDynamicSharedMemorySize, SMEM_SZ);
    cudaFuncSetAttribute(binconv_wino_inverse,
                         cudaFuncAttributeMaxDynamicSharedMemorySize, INV_SMEM);

    transform_x_kernel<<<NB * HP, 256>>>(x);
    winograd_x_kernel<<<NTILE * 128 / 256, 256>>>();
    winograd_w_kernel<<<(CO * CI + 255) / 256, 256>>>(weight);

    dim3 ggrid(NTILE / 128, 16);
    binconv_wino_gemm<<<ggrid, 512, SMEM_SZ>>>();

    dim3 igrid(NB * 28, CO / 64);
    binconv_wino_inverse<<<igrid, 256, INV_SMEM>>>(bias, out);
}